// round 1
// baseline (speedup 1.0000x reference)
#include <cuda_runtime.h>

#define S2v 32
#define Bv  32
#define CIv 64
#define COv 64
#define Lv  256
#define Kv  3
#define Av  16
#define Hv  128
#define NWv (CIv*COv*Kv)   /* 12288 columns of W2, ordered i*192 + o*3 + k */
#define EPSv 1e-5f

// Scratch (device globals: allocation-free per harness rules)
__device__ float g_h[Bv*Lv*Hv];              // 4 MB   relu(LN(z@W1))
__device__ float g_bias[Bv*Lv*COv];          // 2 MB   bias[b][l][o]
__device__ float g_w[(size_t)Bv*Lv*NWv];     // 403 MB w[b][l][i*192+o*3+k]

// ---------------------------------------------------------------------------
// K1: hypernet rows. One block per (b,l) row, 128 threads.
// ---------------------------------------------------------------------------
__global__ void k1_hyper(const float* __restrict__ z,
                         const float* __restrict__ W1,  const float* __restrict__ b1,
                         const float* __restrict__ g1,  const float* __restrict__ be1,
                         const float* __restrict__ Wb1, const float* __restrict__ bb1,
                         const float* __restrict__ gb1, const float* __restrict__ beb1,
                         const float* __restrict__ Wb2, const float* __restrict__ bb2)
{
    int r = blockIdx.x;            // r = b*L + l
    int j = threadIdx.x;           // 0..127
    __shared__ float sz[Av];
    __shared__ float s_hb[Hv];
    __shared__ float red[8];

    if (j < Av) sz[j] = z[r*Av + j];
    __syncthreads();

    // ---- weight hypernet: h = relu(LN(z@W1 + b1)) ----
    float acc = b1[j];
#pragma unroll
    for (int a = 0; a < Av; a++) acc += sz[a] * W1[a*Hv + j];

    float v = acc, v2 = acc*acc;
#pragma unroll
    for (int off = 16; off > 0; off >>= 1) {
        v  += __shfl_xor_sync(0xffffffffu, v,  off);
        v2 += __shfl_xor_sync(0xffffffffu, v2, off);
    }
    int wid = j >> 5, lid = j & 31;
    if (lid == 0) { red[wid] = v; red[4 + wid] = v2; }
    __syncthreads();
    float sum = red[0] + red[1] + red[2] + red[3];
    float sq  = red[4] + red[5] + red[6] + red[7];
    float mu  = sum * (1.0f/Hv);
    float var = sq  * (1.0f/Hv) - mu*mu;
    float hn  = (acc - mu) * rsqrtf(var + EPSv) * g1[j] + be1[j];
    hn = fmaxf(hn, 0.0f);
    g_h[r*Hv + j] = hn;
    __syncthreads();  // red reads done before reuse below

    // ---- bias hypernet: hb = relu(LN(z@Wb1 + bb1)) ----
    float accb = bb1[j];
#pragma unroll
    for (int a = 0; a < Av; a++) accb += sz[a] * Wb1[a*Hv + j];

    float u = accb, u2 = accb*accb;
#pragma unroll
    for (int off = 16; off > 0; off >>= 1) {
        u  += __shfl_xor_sync(0xffffffffu, u,  off);
        u2 += __shfl_xor_sync(0xffffffffu, u2, off);
    }
    if (lid == 0) { red[wid] = u; red[4 + wid] = u2; }
    __syncthreads();
    float sumb = red[0] + red[1] + red[2] + red[3];
    float sqb  = red[4] + red[5] + red[6] + red[7];
    float mub  = sumb * (1.0f/Hv);
    float varb = sqb  * (1.0f/Hv) - mub*mub;
    float hbn  = (accb - mub) * rsqrtf(varb + EPSv) * gb1[j] + beb1[j];
    hbn = fmaxf(hbn, 0.0f);
    s_hb[j] = hbn;
    __syncthreads();

    // ---- bias[o] = hb @ Wb2 + bb2 ----
    if (j < COv) {
        float bo = bb2[j];
#pragma unroll 8
        for (int hh = 0; hh < Hv; hh++) bo += s_hb[hh] * Wb2[hh*COv + j];
        g_bias[r*COv + j] = bo;
    }
}

// ---------------------------------------------------------------------------
// K2: SGEMM  g_w[8192,12288] = g_h[8192,128] @ W2[128,12288] + b2
// 128x128 tile, BK=8, 256 threads, 8x8 microtile (split 4+4).
// ---------------------------------------------------------------------------
__global__ void __launch_bounds__(256, 2)
k2_gemm(const float* __restrict__ W2, const float* __restrict__ b2)
{
    __shared__ float As[8][128];
    __shared__ float Bs[8][128];

    int row0 = blockIdx.y * 128;
    int col0 = blockIdx.x * 128;
    int tid  = threadIdx.x;

    int arow = tid >> 1;            // 0..127
    int ak   = (tid & 1) * 4;       // 0 or 4
    int brow = tid >> 5;            // 0..7
    int bcol = (tid & 31) * 4;      // 0..124

    int tx = tid & 15, ty = tid >> 4;

    float acc[8][8];
#pragma unroll
    for (int i = 0; i < 8; i++)
#pragma unroll
        for (int j = 0; j < 8; j++) acc[i][j] = 0.0f;

    for (int kb = 0; kb < Hv; kb += 8) {
        float4 a4 = *(const float4*)&g_h[(row0 + arow)*Hv + kb + ak];
        float4 b4 = *(const float4*)&W2[(size_t)(kb + brow)*NWv + col0 + bcol];
        As[ak+0][arow] = a4.x; As[ak+1][arow] = a4.y;
        As[ak+2][arow] = a4.z; As[ak+3][arow] = a4.w;
        *(float4*)&Bs[brow][bcol] = b4;
        __syncthreads();

#pragma unroll
        for (int kk = 0; kk < 8; kk++) {
            float af[8], bf[8];
            *(float4*)(af)   = *(const float4*)&As[kk][ty*4];
            *(float4*)(af+4) = *(const float4*)&As[kk][64 + ty*4];
            *(float4*)(bf)   = *(const float4*)&Bs[kk][tx*4];
            *(float4*)(bf+4) = *(const float4*)&Bs[kk][64 + tx*4];
#pragma unroll
            for (int i = 0; i < 8; i++)
#pragma unroll
                for (int j = 0; j < 8; j++)
                    acc[i][j] += af[i] * bf[j];
        }
        __syncthreads();
    }

    // epilogue: + b2, write g_w
    float4 blo = *(const float4*)&b2[col0 + tx*4];
    float4 bhi = *(const float4*)&b2[col0 + 64 + tx*4];
#pragma unroll
    for (int i = 0; i < 8; i++) {
        int row = row0 + ((i < 4) ? (ty*4 + i) : (64 + ty*4 + (i-4)));
        float* wr = &g_w[(size_t)row * NWv];
        float4 o0 = make_float4(acc[i][0]+blo.x, acc[i][1]+blo.y,
                                acc[i][2]+blo.z, acc[i][3]+blo.w);
        float4 o1 = make_float4(acc[i][4]+bhi.x, acc[i][5]+bhi.y,
                                acc[i][6]+bhi.z, acc[i][7]+bhi.w);
        *(float4*)&wr[col0 + tx*4]      = o0;
        *(float4*)&wr[col0 + 64 + tx*4] = o1;
    }
}

// ---------------------------------------------------------------------------
// K3: conv + bias. One block per (b, 4 l-positions). 256 threads.
// thread t: o = t & 63, sg = t >> 6;  owns s in {sg, sg+4, ..., sg+28}
// ---------------------------------------------------------------------------
__global__ void __launch_bounds__(256, 2)
k3_conv(const float* __restrict__ x, float* __restrict__ out)
{
    int bidx = blockIdx.x;
    int b  = bidx >> 6;
    int l0 = (bidx & 63) * 4;
    int t  = threadIdx.x;
    int o  = t & 63;
    int sg = t >> 6;

    __shared__ float xs[32][16][8];        // 16 KB: x[s][i_sub][l0-1+j]
    __shared__ float ws4[4][4][192];       // 12 KB: [di][dl][o*3+k]

    int r0 = b*Lv + l0;

    float acc[8][4];
#pragma unroll
    for (int dl = 0; dl < 4; dl++) {
        float bv = g_bias[(r0 + dl)*COv + o];
#pragma unroll
        for (int si = 0; si < 8; si++) acc[si][dl] = bv;
    }

    for (int ic = 0; ic < 4; ic++) {       // i chunks of 16
        __syncthreads();                   // previous xs use done
        for (int uu = t; uu < 32*16*6; uu += 256) {
            int s    = uu / 96;
            int rest = uu % 96;
            int ii   = rest / 6;
            int j    = rest % 6;
            int l    = l0 - 1 + j;
            float v  = 0.0f;
            if (l >= 0 && l < Lv)
                v = x[((size_t)(s*Bv + b)*CIv + ic*16 + ii)*Lv + l];
            xs[s][ii][j] = v;
        }
        __syncthreads();

        for (int i4 = 0; i4 < 4; i4++) {   // i sub-groups of 4
            __syncthreads();               // previous ws4 use done
            int ibase = ic*16 + i4*4;
            for (int u4 = t; u4 < 768; u4 += 256) {
                int f    = u4 * 4;
                int dl   = f / 768;
                int rest = f % 768;        // di*192 + c
                float4 wv = *(const float4*)&g_w[(size_t)(r0 + dl)*NWv + ibase*192 + rest];
                int di = rest / 192, c = rest % 192;
                *(float4*)&ws4[di][dl][c] = wv;
            }
            __syncthreads();

#pragma unroll
            for (int di = 0; di < 4; di++) {
                int ii = i4*4 + di;
                float w00 = ws4[di][0][o*3+0], w01 = ws4[di][0][o*3+1], w02 = ws4[di][0][o*3+2];
                float w10 = ws4[di][1][o*3+0], w11 = ws4[di][1][o*3+1], w12 = ws4[di][1][o*3+2];
                float w20 = ws4[di][2][o*3+0], w21 = ws4[di][2][o*3+1], w22 = ws4[di][2][o*3+2];
                float w30 = ws4[di][3][o*3+0], w31 = ws4[di][3][o*3+1], w32 = ws4[di][3][o*3+2];
#pragma unroll
                for (int si = 0; si < 8; si++) {
                    int s = si*4 + sg;
                    float4 x0 = *(const float4*)&xs[s][ii][0];
                    float4 x1 = *(const float4*)&xs[s][ii][4];
                    acc[si][0] += x0.x*w00 + x0.y*w01 + x0.z*w02;
                    acc[si][1] += x0.y*w10 + x0.z*w11 + x0.w*w12;
                    acc[si][2] += x0.z*w20 + x0.w*w21 + x1.x*w22;
                    acc[si][3] += x0.w*w30 + x1.x*w31 + x1.y*w32;
                }
            }
        }
    }

#pragma unroll
    for (int si = 0; si < 8; si++) {
        int s = si*4 + sg;
        float4 ov = make_float4(acc[si][0], acc[si][1], acc[si][2], acc[si][3]);
        *(float4*)&out[((size_t)(s*Bv + b)*COv + o)*Lv + l0] = ov;
    }
}

// ---------------------------------------------------------------------------
extern "C" void kernel_launch(void* const* d_in, const int* in_sizes, int n_in,
                              void* d_out, int out_size)
{
    const float* x    = (const float*)d_in[0];
    const float* z    = (const float*)d_in[1];
    const float* W1   = (const float*)d_in[2];
    const float* b1   = (const float*)d_in[3];
    const float* g1   = (const float*)d_in[4];
    const float* be1  = (const float*)d_in[5];
    const float* W2   = (const float*)d_in[6];
    const float* b2   = (const float*)d_in[7];
    const float* Wb1  = (const float*)d_in[8];
    const float* bb1  = (const float*)d_in[9];
    const float* gb1  = (const float*)d_in[10];
    const float* beb1 = (const float*)d_in[11];
    const float* Wb2  = (const float*)d_in[12];
    const float* bb2  = (const float*)d_in[13];
    float* out = (float*)d_out;

    k1_hyper<<<Bv*Lv, Hv>>>(z, W1, b1, g1, be1, Wb1, bb1, gb1, beb1, Wb2, bb2);

    dim3 g2(NWv/128, (Bv*Lv)/128);   // (96, 64)
    k2_gemm<<<g2, 256>>>(W2, b2);

    k3_conv<<<Bv*(Lv/4), 256>>>(x, out);
}

// round 3
// speedup vs baseline: 1.2466x; 1.2466x over previous
#include <cuda_runtime.h>
#include <cuda_bf16.h>
#include <cstdint>

#define S2v 32
#define Bv  32
#define CIv 64
#define COv 64
#define Lv  256
#define Kv  3
#define Av  16
#define Hv  128
#define NWv (CIv*COv*Kv)   /* 12288 columns of W2, ordered i*192 + o*3 + k */
#define EPSv 1e-5f
#define ROWS (Bv*Lv)       /* 8192 */

// ---------------- device scratch (allocation-free) ----------------
__device__ __nv_bfloat16 g_Ah[ROWS*Hv];          // 2 MB  hi(h)
__device__ __nv_bfloat16 g_Al[ROWS*Hv];          // 2 MB  lo(h)
__device__ __nv_bfloat16 g_Bh[(size_t)NWv*Hv];   // 3 MB  hi(W2^T)  [n][k]
__device__ __nv_bfloat16 g_Bl[(size_t)NWv*Hv];   // 3 MB  lo(W2^T)
__device__ float g_bias[ROWS*COv];               // 2 MB
__device__ float g_w[(size_t)ROWS*NWv];          // 403 MB

// ---------------------------------------------------------------------------
// K1: hypernet rows. One block per (b,l) row, 128 threads.
// Writes bf16 hi/lo split of h, plus conv bias.
// ---------------------------------------------------------------------------
__global__ void k1_hyper(const float* __restrict__ z,
                         const float* __restrict__ W1,  const float* __restrict__ b1,
                         const float* __restrict__ g1,  const float* __restrict__ be1,
                         const float* __restrict__ Wb1, const float* __restrict__ bb1,
                         const float* __restrict__ gb1, const float* __restrict__ beb1,
                         const float* __restrict__ Wb2, const float* __restrict__ bb2)
{
    int r = blockIdx.x;
    int j = threadIdx.x;
    __shared__ float sz[Av];
    __shared__ float s_hb[Hv];
    __shared__ float red[8];

    if (j < Av) sz[j] = z[r*Av + j];
    __syncthreads();

    float acc = b1[j];
#pragma unroll
    for (int a = 0; a < Av; a++) acc += sz[a] * W1[a*Hv + j];

    float v = acc, v2 = acc*acc;
#pragma unroll
    for (int off = 16; off > 0; off >>= 1) {
        v  += __shfl_xor_sync(0xffffffffu, v,  off);
        v2 += __shfl_xor_sync(0xffffffffu, v2, off);
    }
    int wid = j >> 5, lid = j & 31;
    if (lid == 0) { red[wid] = v; red[4 + wid] = v2; }
    __syncthreads();
    float sum = red[0] + red[1] + red[2] + red[3];
    float sq  = red[4] + red[5] + red[6] + red[7];
    float mu  = sum * (1.0f/Hv);
    float var = sq  * (1.0f/Hv) - mu*mu;
    float hn  = (acc - mu) * rsqrtf(var + EPSv) * g1[j] + be1[j];
    hn = fmaxf(hn, 0.0f);
    __nv_bfloat16 hi = __float2bfloat16(hn);
    g_Ah[r*Hv + j] = hi;
    g_Al[r*Hv + j] = __float2bfloat16(hn - __bfloat162float(hi));
    __syncthreads();

    float accb = bb1[j];
#pragma unroll
    for (int a = 0; a < Av; a++) accb += sz[a] * Wb1[a*Hv + j];

    float u = accb, u2 = accb*accb;
#pragma unroll
    for (int off = 16; off > 0; off >>= 1) {
        u  += __shfl_xor_sync(0xffffffffu, u,  off);
        u2 += __shfl_xor_sync(0xffffffffu, u2, off);
    }
    if (lid == 0) { red[wid] = u; red[4 + wid] = u2; }
    __syncthreads();
    float sumb = red[0] + red[1] + red[2] + red[3];
    float sqb  = red[4] + red[5] + red[6] + red[7];
    float mub  = sumb * (1.0f/Hv);
    float varb = sqb  * (1.0f/Hv) - mub*mub;
    float hbn  = (accb - mub) * rsqrtf(varb + EPSv) * gb1[j] + beb1[j];
    hbn = fmaxf(hbn, 0.0f);
    s_hb[j] = hbn;
    __syncthreads();

    if (j < COv) {
        float bo = bb2[j];
#pragma unroll 8
        for (int hh = 0; hh < Hv; hh++) bo += s_hb[hh] * Wb2[hh*COv + j];
        g_bias[r*COv + j] = bo;
    }
}

// ---------------------------------------------------------------------------
// K-prep: transpose + split W2[128, 12288] f32 -> Bh/Bl[12288, 128] bf16
// ---------------------------------------------------------------------------
__global__ void k_prep(const float* __restrict__ W2)
{
    __shared__ float t[32][33];
    int n0 = blockIdx.x * 32;
    int k0 = blockIdx.y * 32;
    int tx = threadIdx.x & 31, ty = threadIdx.x >> 5;   // 32 x 8

#pragma unroll
    for (int i = 0; i < 4; i++) {
        int k = k0 + ty + i*8;
        t[ty + i*8][tx] = W2[(size_t)k * NWv + n0 + tx];
    }
    __syncthreads();
#pragma unroll
    for (int i = 0; i < 4; i++) {
        int n = n0 + ty + i*8;
        float val = t[tx][ty + i*8];
        __nv_bfloat16 hi = __float2bfloat16(val);
        g_Bh[(size_t)n * Hv + k0 + tx] = hi;
        g_Bl[(size_t)n * Hv + k0 + tx] = __float2bfloat16(val - __bfloat162float(hi));
    }
}

// ---------------------------------------------------------------------------
// K2-HMMA: warp-level mma.sync bf16 split-3 GEMM
//   g_w[8192,12288] = h @ W2 + b2
// CTA: 128x128 tile, K=128 resident. 8 warps, warp tile 64x32.
// SMEM rows padded to 272B -> conflict-free fragment LDS.
// ---------------------------------------------------------------------------
#define PADB 272                 /* 136 bf16 per row */
#define OFF_AH 0
#define OFF_AL 34816
#define OFF_BH 69632
#define OFF_BL 104448
#define SMEM_K2 139264

__device__ __forceinline__ void mma16816(float* c, uint32_t a0, uint32_t a1,
                                         uint32_t a2, uint32_t a3,
                                         uint32_t b0, uint32_t b1)
{
    asm volatile(
        "mma.sync.aligned.m16n8k16.row.col.f32.bf16.bf16.f32 "
        "{%0,%1,%2,%3}, {%4,%5,%6,%7}, {%8,%9}, {%0,%1,%2,%3};"
        : "+f"(c[0]), "+f"(c[1]), "+f"(c[2]), "+f"(c[3])
        : "r"(a0), "r"(a1), "r"(a2), "r"(a3), "r"(b0), "r"(b1));
}

__global__ void __launch_bounds__(256, 1)
k2_hmma(const float* __restrict__ b2)
{
    extern __shared__ char sm[];
    const int tid  = threadIdx.x;
    const int wid  = tid >> 5, lane = tid & 31;
    const int row0 = blockIdx.y * 128;
    const int col0 = blockIdx.x * 128;
    const int wm   = (wid >> 2) * 64;     // warp m offset
    const int wn   = (wid & 3) * 32;      // warp n offset

    // ---- load all 4 tiles (A hi/lo by m, B hi/lo by n), padded rows ----
    for (int u = tid; u < 2048; u += 256) {
        int r = u >> 4, j = u & 15;      // row 0..127, 16B chunk 0..15
        size_t ga = (size_t)(row0 + r) * Hv + j*8;
        size_t gb = (size_t)(col0 + r) * Hv + j*8;
        *(uint4*)(sm + OFF_AH + r*PADB + j*16) = *(const uint4*)&g_Ah[ga];
        *(uint4*)(sm + OFF_AL + r*PADB + j*16) = *(const uint4*)&g_Al[ga];
        *(uint4*)(sm + OFF_BH + r*PADB + j*16) = *(const uint4*)&g_Bh[gb];
        *(uint4*)(sm + OFF_BL + r*PADB + j*16) = *(const uint4*)&g_Bl[gb];
    }
    __syncthreads();

    float acc[4][4][4];
#pragma unroll
    for (int mf = 0; mf < 4; mf++)
#pragma unroll
        for (int nf = 0; nf < 4; nf++)
#pragma unroll
            for (int q = 0; q < 4; q++) acc[mf][nf][q] = 0.0f;

    const int aoff = (wm + (lane >> 2)) * PADB + (lane & 3) * 4;
    const int boff = (wn + (lane >> 2)) * PADB + (lane & 3) * 4;

    const int AO[3] = {OFF_AH, OFF_AH, OFF_AL};
    const int BO[3] = {OFF_BH, OFF_BL, OFF_BH};

#pragma unroll
    for (int sp = 0; sp < 3; sp++) {
        const char* Ab = sm + AO[sp] + aoff;
        const char* Bb = sm + BO[sp] + boff;
#pragma unroll
        for (int ks = 0; ks < 8; ks++) {
            uint32_t br0[4], br1[4];
#pragma unroll
            for (int nf = 0; nf < 4; nf++) {
                br0[nf] = *(const uint32_t*)(Bb + nf*2176 + ks*32);
                br1[nf] = *(const uint32_t*)(Bb + nf*2176 + ks*32 + 16);
            }
#pragma unroll
            for (int mf = 0; mf < 4; mf++) {
                const char* Am = Ab + mf*4352 + ks*32;
                uint32_t a0 = *(const uint32_t*)(Am);
                uint32_t a1 = *(const uint32_t*)(Am + 2176);
                uint32_t a2 = *(const uint32_t*)(Am + 16);
                uint32_t a3 = *(const uint32_t*)(Am + 2192);
#pragma unroll
                for (int nf = 0; nf < 4; nf++)
                    mma16816(acc[mf][nf], a0, a1, a2, a3, br0[nf], br1[nf]);
            }
        }
    }

    // ---- epilogue: + b2, write g_w ----
    float2 bv[4];
#pragma unroll
    for (int nf = 0; nf < 4; nf++)
        bv[nf] = *(const float2*)&b2[col0 + wn + nf*8 + (lane & 3)*2];

#pragma unroll
    for (int mf = 0; mf < 4; mf++) {
        int r = row0 + wm + mf*16 + (lane >> 2);
#pragma unroll
        for (int nf = 0; nf < 4; nf++) {
            float* p = &g_w[(size_t)r * NWv + col0 + wn + nf*8 + (lane & 3)*2];
            float2 lo = make_float2(acc[mf][nf][0] + bv[nf].x,
                                    acc[mf][nf][1] + bv[nf].y);
            float2 hi = make_float2(acc[mf][nf][2] + bv[nf].x,
                                    acc[mf][nf][3] + bv[nf].y);
            *(float2*)p = lo;
            *(float2*)(p + (size_t)8 * NWv) = hi;
        }
    }
}

// ---------------------------------------------------------------------------
// K3: conv + bias. One block per (b, 4 l-positions). 256 threads.
// ---------------------------------------------------------------------------
__global__ void __launch_bounds__(256, 2)
k3_conv(const float* __restrict__ x, float* __restrict__ out)
{
    int bidx = blockIdx.x;
    int b  = bidx >> 6;
    int l0 = (bidx & 63) * 4;
    int t  = threadIdx.x;
    int o  = t & 63;
    int sg = t >> 6;

    __shared__ float xs[32][16][8];
    __shared__ float ws4[4][4][192];

    int r0 = b*Lv + l0;

    float acc[8][4];
#pragma unroll
    for (int dl = 0; dl < 4; dl++) {
        float bv = g_bias[(r0 + dl)*COv + o];
#pragma unroll
        for (int si = 0; si < 8; si++) acc[si][dl] = bv;
    }

    for (int ic = 0; ic < 4; ic++) {
        __syncthreads();
        for (int uu = t; uu < 32*16*6; uu += 256) {
            int s    = uu / 96;
            int rest = uu % 96;
            int ii   = rest / 6;
            int j    = rest % 6;
            int l    = l0 - 1 + j;
            float v  = 0.0f;
            if (l >= 0 && l < Lv)
                v = x[((size_t)(s*Bv + b)*CIv + ic*16 + ii)*Lv + l];
            xs[s][ii][j] = v;
        }
        __syncthreads();

        for (int i4 = 0; i4 < 4; i4++) {
            __syncthreads();
            int ibase = ic*16 + i4*4;
            for (int u4 = t; u4 < 768; u4 += 256) {
                int f    = u4 * 4;
                int dl   = f / 768;
                int rest = f % 768;
                float4 wv = *(const float4*)&g_w[(size_t)(r0 + dl)*NWv + ibase*192 + rest];
                int di = rest / 192, c = rest % 192;
                *(float4*)&ws4[di][dl][c] = wv;
            }
            __syncthreads();

#pragma unroll
            for (int di = 0; di < 4; di++) {
                int ii = i4*4 + di;
                float w00 = ws4[di][0][o*3+0], w01 = ws4[di][0][o*3+1], w02 = ws4[di][0][o*3+2];
                float w10 = ws4[di][1][o*3+0], w11 = ws4[di][1][o*3+1], w12 = ws4[di][1][o*3+2];
                float w20 = ws4[di][2][o*3+0], w21 = ws4[di][2][o*3+1], w22 = ws4[di][2][o*3+2];
                float w30 = ws4[di][3][o*3+0], w31 = ws4[di][3][o*3+1], w32 = ws4[di][3][o*3+2];
#pragma unroll
                for (int si = 0; si < 8; si++) {
                    int s = si*4 + sg;
                    float4 x0 = *(const float4*)&xs[s][ii][0];
                    float4 x1 = *(const float4*)&xs[s][ii][4];
                    acc[si][0] += x0.x*w00 + x0.y*w01 + x0.z*w02;
                    acc[si][1] += x0.y*w10 + x0.z*w11 + x0.w*w12;
                    acc[si][2] += x0.z*w20 + x0.w*w21 + x1.x*w22;
                    acc[si][3] += x0.w*w30 + x1.x*w31 + x1.y*w32;
                }
            }
        }
    }

#pragma unroll
    for (int si = 0; si < 8; si++) {
        int s = si*4 + sg;
        float4 ov = make_float4(acc[si][0], acc[si][1], acc[si][2], acc[si][3]);
        *(float4*)&out[((size_t)(s*Bv + b)*COv + o)*Lv + l0] = ov;
    }
}

// ---------------------------------------------------------------------------
extern "C" void kernel_launch(void* const* d_in, const int* in_sizes, int n_in,
                              void* d_out, int out_size)
{
    const float* x    = (const float*)d_in[0];
    const float* z    = (const float*)d_in[1];
    const float* W1   = (const float*)d_in[2];
    const float* b1   = (const float*)d_in[3];
    const float* g1   = (const float*)d_in[4];
    const float* be1  = (const float*)d_in[5];
    const float* W2   = (const float*)d_in[6];
    const float* b2   = (const float*)d_in[7];
    const float* Wb1  = (const float*)d_in[8];
    const float* bb1  = (const float*)d_in[9];
    const float* gb1  = (const float*)d_in[10];
    const float* beb1 = (const float*)d_in[11];
    const float* Wb2  = (const float*)d_in[12];
    const float* bb2  = (const float*)d_in[13];
    float* out = (float*)d_out;

    cudaFuncSetAttribute(k2_hmma, cudaFuncAttributeMaxDynamicSharedMemorySize,
                         SMEM_K2);

    k1_hyper<<<ROWS, Hv>>>(z, W1, b1, g1, be1, Wb1, bb1, gb1, beb1, Wb2, bb2);

    dim3 gp(NWv/32, Hv/32);          // (384, 4)
    k_prep<<<gp, 256>>>(W2);

    dim3 g2(NWv/128, ROWS/128);      // (96, 64)
    k2_hmma<<<g2, 256, SMEM_K2>>>(b2);

    k3_conv<<<Bv*(Lv/4), 256>>>(x, out);
}

// round 6
// speedup vs baseline: 1.3000x; 1.0428x over previous
#include <cuda_runtime.h>
#include <cuda_bf16.h>
#include <cstdint>

#define S2v 32
#define Bv  32
#define CIv 64
#define COv 64
#define Lv  256
#define Kv  3
#define Av  16
#define Hv  128
#define NWv (CIv*COv*Kv)   /* 12288 */
#define EPSv 1e-5f
#define ROWS (Bv*Lv)       /* 8192 */

// ---------------- device scratch (allocation-free) ----------------
__device__ __nv_bfloat16 g_Ah[ROWS*Hv];            // hi(h)
__device__ __nv_bfloat16 g_Al[ROWS*Hv];            // lo(h)
__device__ __nv_bfloat16 g_Bh[(size_t)NWv*Hv];     // hi(W2^T) permuted rows
__device__ __nv_bfloat16 g_Bl[(size_t)NWv*Hv];
__device__ float g_bias[ROWS*COv];
__device__ __nv_bfloat16 g_wh[(size_t)ROWS*NWv];   // 201 MB  hi(w), cols [k][o][i]
__device__ __nv_bfloat16 g_wl[(size_t)ROWS*NWv];   // 201 MB  lo(w)

// ---------------- helpers ----------------
__device__ __forceinline__ uint32_t s2u(const void* p) {
    uint32_t a;
    asm("{ .reg .u64 t; cvta.to.shared.u64 t, %1; cvt.u32.u64 %0, t; }"
        : "=r"(a) : "l"(p));
    return a;
}
__device__ __forceinline__ void mma16816(float* c, uint32_t a0, uint32_t a1,
                                         uint32_t a2, uint32_t a3,
                                         uint32_t b0, uint32_t b1)
{
    asm volatile(
        "mma.sync.aligned.m16n8k16.row.col.f32.bf16.bf16.f32 "
        "{%0,%1,%2,%3}, {%4,%5,%6,%7}, {%8,%9}, {%0,%1,%2,%3};"
        : "+f"(c[0]), "+f"(c[1]), "+f"(c[2]), "+f"(c[3])
        : "r"(a0), "r"(a1), "r"(a2), "r"(a3), "r"(b0), "r"(b1));
}
__device__ __forceinline__ void ldm_x4(uint32_t* r, uint32_t addr) {
    asm volatile("ldmatrix.sync.aligned.m8n8.x4.shared.b16 {%0,%1,%2,%3}, [%4];"
        : "=r"(r[0]), "=r"(r[1]), "=r"(r[2]), "=r"(r[3]) : "r"(addr));
}
__device__ __forceinline__ void ldm_x2(uint32_t* r, uint32_t addr) {
    asm volatile("ldmatrix.sync.aligned.m8n8.x2.shared.b16 {%0,%1}, [%2];"
        : "=r"(r[0]), "=r"(r[1]) : "r"(addr));
}
#define CP16(dst, src) \
    asm volatile("cp.async.cg.shared.global [%0], [%1], 16;" :: "r"(dst), "l"(src))
#define CPCOMMIT() asm volatile("cp.async.commit_group;")
#define CPWAIT(n)  asm volatile("cp.async.wait_group %0;" :: "n"(n))

// ---------------------------------------------------------------------------
// K1: hypernet rows. One block per (b,l) row, 128 threads.
// ---------------------------------------------------------------------------
__global__ void k1_hyper(const float* __restrict__ z,
                         const float* __restrict__ W1,  const float* __restrict__ b1,
                         const float* __restrict__ g1,  const float* __restrict__ be1,
                         const float* __restrict__ Wb1, const float* __restrict__ bb1,
                         const float* __restrict__ gb1, const float* __restrict__ beb1,
                         const float* __restrict__ Wb2, const float* __restrict__ bb2)
{
    int r = blockIdx.x;
    int j = threadIdx.x;
    __shared__ float sz[Av];
    __shared__ float s_hb[Hv];
    __shared__ float red[8];

    if (j < Av) sz[j] = z[r*Av + j];
    __syncthreads();

    float acc = b1[j];
#pragma unroll
    for (int a = 0; a < Av; a++) acc += sz[a] * W1[a*Hv + j];

    float v = acc, v2 = acc*acc;
#pragma unroll
    for (int off = 16; off > 0; off >>= 1) {
        v  += __shfl_xor_sync(0xffffffffu, v,  off);
        v2 += __shfl_xor_sync(0xffffffffu, v2, off);
    }
    int wid = j >> 5, lid = j & 31;
    if (lid == 0) { red[wid] = v; red[4 + wid] = v2; }
    __syncthreads();
    float sum = red[0] + red[1] + red[2] + red[3];
    float sq  = red[4] + red[5] + red[6] + red[7];
    float mu  = sum * (1.0f/Hv);
    float var = sq  * (1.0f/Hv) - mu*mu;
    float hn  = (acc - mu) * rsqrtf(var + EPSv) * g1[j] + be1[j];
    hn = fmaxf(hn, 0.0f);
    __nv_bfloat16 hi = __float2bfloat16(hn);
    g_Ah[r*Hv + j] = hi;
    g_Al[r*Hv + j] = __float2bfloat16(hn - __bfloat162float(hi));
    __syncthreads();

    float accb = bb1[j];
#pragma unroll
    for (int a = 0; a < Av; a++) accb += sz[a] * Wb1[a*Hv + j];

    float u = accb, u2 = accb*accb;
#pragma unroll
    for (int off = 16; off > 0; off >>= 1) {
        u  += __shfl_xor_sync(0xffffffffu, u,  off);
        u2 += __shfl_xor_sync(0xffffffffu, u2, off);
    }
    if (lid == 0) { red[wid] = u; red[4 + wid] = u2; }
    __syncthreads();
    float sumb = red[0] + red[1] + red[2] + red[3];
    float sqb  = red[4] + red[5] + red[6] + red[7];
    float mub  = sumb * (1.0f/Hv);
    float varb = sqb  * (1.0f/Hv) - mub*mub;
    float hbn  = (accb - mub) * rsqrtf(varb + EPSv) * gb1[j] + beb1[j];
    hbn = fmaxf(hbn, 0.0f);
    s_hb[j] = hbn;
    __syncthreads();

    if (j < COv) {
        float bo = bb2[j];
#pragma unroll 8
        for (int hh = 0; hh < Hv; hh++) bo += s_hb[hh] * Wb2[hh*COv + j];
        g_bias[r*COv + j] = bo;
    }
}

// ---------------------------------------------------------------------------
// K-prep: transpose + split + PERMUTE W2[128, 12288] -> Bh/Bl rows n' = k*4096+o*64+i
// ---------------------------------------------------------------------------
__global__ void k_prep(const float* __restrict__ W2)
{
    __shared__ float t[32][33];
    int n0 = blockIdx.x * 32;
    int k0 = blockIdx.y * 32;
    int tx = threadIdx.x & 31, ty = threadIdx.x >> 5;   // 32 x 8

#pragma unroll
    for (int i = 0; i < 4; i++) {
        int k = k0 + ty + i*8;
        t[ty + i*8][tx] = W2[(size_t)k * NWv + n0 + tx];
    }
    __syncthreads();
#pragma unroll
    for (int i = 0; i < 4; i++) {
        int n = n0 + ty + i*8;
        int i_ = n / 192, rest = n % 192;
        int o_ = rest / 3, k_ = rest % 3;
        int np = k_*4096 + o_*64 + i_;
        float val = t[tx][ty + i*8];
        __nv_bfloat16 hi = __float2bfloat16(val);
        g_Bh[(size_t)np * Hv + k0 + tx] = hi;
        g_Bl[(size_t)np * Hv + k0 + tx] = __float2bfloat16(val - __bfloat162float(hi));
    }
}

// ---------------------------------------------------------------------------
// K2-HMMA: g_wh/g_wl[8192, 12288(perm)] = bf16split(h @ W2p + b2p)
// 128x128 tile, K=128, cp.async 2-phase pipeline, split-3 MMA.
// ---------------------------------------------------------------------------
#define PADB 272
#define OFF_AH 0
#define OFF_AL 34816
#define OFF_BH 69632
#define OFF_BL 104448
#define SMEM_K2 139264

__device__ __forceinline__ void k2_split_mma(const char* Ab, const char* Bb,
                                             float acc[4][4][4])
{
#pragma unroll
    for (int ks = 0; ks < 8; ks++) {
        uint32_t br0[4], br1[4];
#pragma unroll
        for (int nf = 0; nf < 4; nf++) {
            br0[nf] = *(const uint32_t*)(Bb + nf*2176 + ks*32);
            br1[nf] = *(const uint32_t*)(Bb + nf*2176 + ks*32 + 16);
        }
#pragma unroll
        for (int mf = 0; mf < 4; mf++) {
            const char* Am = Ab + mf*4352 + ks*32;
            uint32_t a0 = *(const uint32_t*)(Am);
            uint32_t a1 = *(const uint32_t*)(Am + 2176);
            uint32_t a2 = *(const uint32_t*)(Am + 16);
            uint32_t a3 = *(const uint32_t*)(Am + 2192);
#pragma unroll
            for (int nf = 0; nf < 4; nf++)
                mma16816(acc[mf][nf], a0, a1, a2, a3, br0[nf], br1[nf]);
        }
    }
}

__global__ void __launch_bounds__(256, 1)
k2_hmma(const float* __restrict__ b2)
{
    extern __shared__ char sm[];
    uint32_t smu = s2u(sm);
    const int tid  = threadIdx.x;
    const int wid  = tid >> 5, lane = tid & 31;
    const int row0 = blockIdx.y * 128;
    const int col0 = blockIdx.x * 128;
    const int wm   = (wid >> 2) * 64;
    const int wn   = (wid & 3) * 32;

    // phase-0 loads: Ah, Bh
    for (int u = tid; u < 2048; u += 256) {
        int r = u >> 4, j = u & 15;
        CP16(smu + OFF_AH + r*PADB + j*16, &g_Ah[(size_t)(row0 + r)*Hv + j*8]);
    }
    for (int u = tid; u < 2048; u += 256) {
        int r = u >> 4, j = u & 15;
        CP16(smu + OFF_BH + r*PADB + j*16, &g_Bh[(size_t)(col0 + r)*Hv + j*8]);
    }
    CPCOMMIT();
    // phase-1 loads: Al, Bl
    for (int u = tid; u < 2048; u += 256) {
        int r = u >> 4, j = u & 15;
        CP16(smu + OFF_AL + r*PADB + j*16, &g_Al[(size_t)(row0 + r)*Hv + j*8]);
    }
    for (int u = tid; u < 2048; u += 256) {
        int r = u >> 4, j = u & 15;
        CP16(smu + OFF_BL + r*PADB + j*16, &g_Bl[(size_t)(col0 + r)*Hv + j*8]);
    }
    CPCOMMIT();

    float acc[4][4][4];
#pragma unroll
    for (int mf = 0; mf < 4; mf++)
#pragma unroll
        for (int nf = 0; nf < 4; nf++)
#pragma unroll
            for (int q = 0; q < 4; q++) acc[mf][nf][q] = 0.0f;

    const int aoff = (wm + (lane >> 2)) * PADB + (lane & 3) * 4;
    const int boff = (wn + (lane >> 2)) * PADB + (lane & 3) * 4;

    CPWAIT(1);
    __syncthreads();
    k2_split_mma(sm + OFF_AH + aoff, sm + OFF_BH + boff, acc);   // Ah*Bh
    CPWAIT(0);
    __syncthreads();
    k2_split_mma(sm + OFF_AH + aoff, sm + OFF_BL + boff, acc);   // Ah*Bl
    k2_split_mma(sm + OFF_AL + aoff, sm + OFF_BH + boff, acc);   // Al*Bh

    // epilogue: + permuted b2, split to bf16 hi/lo, write
    float bv[4][2];
#pragma unroll
    for (int nf = 0; nf < 4; nf++) {
#pragma unroll
        for (int e = 0; e < 2; e++) {
            int c = col0 + wn + nf*8 + (lane & 3)*2 + e;
            int i_ = c & 63, o_ = (c >> 6) & 63, kt = c >> 12;
            bv[nf][e] = b2[i_*192 + o_*3 + kt];
        }
    }
#pragma unroll
    for (int mf = 0; mf < 4; mf++) {
        int r = row0 + wm + mf*16 + (lane >> 2);
#pragma unroll
        for (int nf = 0; nf < 4; nf++) {
            int c = col0 + wn + nf*8 + (lane & 3)*2;
#pragma unroll
            for (int half = 0; half < 2; half++) {
                float v0 = acc[mf][nf][half*2+0] + bv[nf][0];
                float v1 = acc[mf][nf][half*2+1] + bv[nf][1];
                __nv_bfloat16 h0 = __float2bfloat16(v0);
                __nv_bfloat16 h1 = __float2bfloat16(v1);
                __nv_bfloat162 hh; hh.x = h0; hh.y = h1;
                __nv_bfloat162 ll;
                ll.x = __float2bfloat16(v0 - __bfloat162float(h0));
                ll.y = __float2bfloat16(v1 - __bfloat162float(h1));
                size_t idx = (size_t)(r + half*8) * NWv + c;
                *(__nv_bfloat162*)&g_wh[idx] = hh;
                *(__nv_bfloat162*)&g_wl[idx] = ll;
            }
        }
    }
}

// ---------------------------------------------------------------------------
// K3-HMMA: conv via tensor cores. CTA = (b, 8 l's). 256 threads.
//   out[s,o,l] = sum_kt sum_i x[s,i,l+kt-1] * w[l][kt][o][i]  + bias
// 3-split bf16 products. smem: xs hi/lo [10][32][64+pad], ws hi/lo [192][64+pad],
// out f32 [s][o][8 l], bias [8][64].
// ---------------------------------------------------------------------------
#define X_STRIDE 144
#define XH_O 0
#define XL_O 46080
#define WH_O 92160
#define WL_O 119808
#define OUT_O 147456
#define BIA_O 212992
#define SMEM_K3 215040

__global__ void __launch_bounds__(256, 1)
k3_hconv(const float* __restrict__ x, float* __restrict__ out)
{
    extern __shared__ char sm[];
    uint32_t smu = s2u(sm);
    const int tid  = threadIdx.x;
    const int wid  = tid >> 5, lane = tid & 31;
    const int b  = blockIdx.x >> 5;
    const int l0 = (blockIdx.x & 31) * 8;
    const int r0 = b*Lv + l0;

    // ---- stage x window [l0-1, l0+8] as bf16 hi/lo, layout [l''][s][i] ----
    for (int u = tid; u < 2048; u += 256) {
        int s = u >> 6, i = u & 63;
        const float* xp = x + ((size_t)(s*Bv + b)*CIv + i)*Lv;
#pragma unroll
        for (int t = 0; t < 10; t++) {
            int l = l0 - 1 + t;
            float v = (l >= 0 && l < Lv) ? __ldg(xp + l) : 0.0f;
            __nv_bfloat16 hi = __float2bfloat16(v);
            *(__nv_bfloat16*)(sm + XH_O + (t*32 + s)*X_STRIDE + i*2) = hi;
            *(__nv_bfloat16*)(sm + XL_O + (t*32 + s)*X_STRIDE + i*2) =
                __float2bfloat16(v - __bfloat162float(hi));
        }
    }
    // ---- stage bias [dl][o] ----
    for (int u = tid; u < 512; u += 256)
        ((float*)(sm + BIA_O))[u] = g_bias[(r0 + (u >> 6))*COv + (u & 63)];

    // warp tiling: mt = wid&1 (s half), q = wid>>1 (o quarter)
    const int mt = wid & 1, q = wid >> 1;
    const uint32_t a_lane = (uint32_t)((lane & 15)*X_STRIDE + (lane >> 4)*16);
    const uint32_t b_lane = (uint32_t)((lane & 7)*X_STRIDE + ((lane >> 3) & 1)*16);

    for (int dl = 0; dl < 8; dl++) {
        __syncthreads();   // xs ready (dl=0) / previous ws reads done
        // stage w row (bf16 hi/lo), insert 16B row padding: [192 rows][128B]
        {
            const __nv_bfloat16* srcH = g_wh + (size_t)(r0 + dl) * NWv;
            const __nv_bfloat16* srcL = g_wl + (size_t)(r0 + dl) * NWv;
            for (int u = tid; u < 1536; u += 256) {
                int r = u >> 3, c8 = u & 7;
                *(uint4*)(sm + WH_O + r*X_STRIDE + c8*16) =
                    *(const uint4*)(srcH + r*64 + c8*8);
                *(uint4*)(sm + WL_O + r*X_STRIDE + c8*16) =
                    *(const uint4*)(srcL + r*64 + c8*8);
            }
        }
        __syncthreads();

        float acc[2][4];
#pragma unroll
        for (int nt = 0; nt < 2; nt++)
#pragma unroll
            for (int e = 0; e < 4; e++) acc[nt][e] = 0.0f;

#pragma unroll
        for (int kt = 0; kt < 3; kt++) {
            uint32_t xrow = (uint32_t)(((dl + kt)*32 + mt*16) * X_STRIDE);
            uint32_t wrow = (uint32_t)((kt*64 + q*16) * X_STRIDE);
#pragma unroll
            for (int ks = 0; ks < 4; ks++) {
                uint32_t col = ks*32;
                uint32_t ah[4], al[4], bh0[2], bh1[2], bl0[2], bl1[2];
                ldm_x4(ah, smu + XH_O + xrow + a_lane + col);
                ldm_x4(al, smu + XL_O + xrow + a_lane + col);
                ldm_x2(bh0, smu + WH_O + wrow + b_lane + col);
                ldm_x2(bh1, smu + WH_O + wrow + 8*X_STRIDE + b_lane + col);
                ldm_x2(bl0, smu + WL_O + wrow + b_lane + col);
                ldm_x2(bl1, smu + WL_O + wrow + 8*X_STRIDE + b_lane + col);
                mma16816(acc[0], ah[0],ah[1],ah[2],ah[3], bh0[0],bh0[1]);
                mma16816(acc[0], ah[0],ah[1],ah[2],ah[3], bl0[0],bl0[1]);
                mma16816(acc[0], al[0],al[1],al[2],al[3], bh0[0],bh0[1]);
                mma16816(acc[1], ah[0],ah[1],ah[2],ah[3], bh1[0],bh1[1]);
                mma16816(acc[1], ah[0],ah[1],ah[2],ah[3], bl1[0],bl1[1]);
                mma16816(acc[1], al[0],al[1],al[2],al[3], bh1[0],bh1[1]);
            }
        }

        // store accumulators + bias into out-tile [s][o][dl]
        {
            float* ob = (float*)(sm + OUT_O);
            const float* bs = (float*)(sm + BIA_O) + dl*64;
            int m = lane >> 2, n2 = (lane & 3)*2;
#pragma unroll
            for (int nt = 0; nt < 2; nt++) {
                int o = q*16 + nt*8 + n2;
                float b0 = bs[o], b1 = bs[o+1];
                int s0 = mt*16 + m;
                ob[(s0*64 + o    )*8 + dl] = acc[nt][0] + b0;
                ob[(s0*64 + o + 1)*8 + dl] = acc[nt][1] + b1;
                ob[((s0+8)*64 + o    )*8 + dl] = acc[nt][2] + b0;
                ob[((s0+8)*64 + o + 1)*8 + dl] = acc[nt][3] + b1;
            }
        }
    }

    __syncthreads();
    // coalesced-sector drain: one thread per (s,o) writes 8 l's (32B)
    {
        const float* ob = (const float*)(sm + OUT_O);
        for (int u = tid; u < 2048; u += 256) {
            int s = u >> 6, o = u & 63;
            float4 v0 = *(const float4*)(ob + u*8);
            float4 v1 = *(const float4*)(ob + u*8 + 4);
            float* dst = out + ((size_t)(s*Bv + b)*COv + o)*Lv + l0;
            *(float4*)dst = v0;
            *(float4*)(dst + 4) = v1;
        }
    }
}

// ---------------------------------------------------------------------------
extern "C" void kernel_launch(void* const* d_in, const int* in_sizes, int n_in,
                              void* d_out, int out_size)
{
    const float* x    = (const float*)d_in[0];
    const float* z    = (const float*)d_in[1];
    const float* W1   = (const float*)d_in[2];
    const float* b1   = (const float*)d_in[3];
    const float* g1   = (const float*)d_in[4];
    const float* be1  = (const float*)d_in[5];
    const float* W2   = (const float*)d_in[6];
    const float* b2   = (const float*)d_in[7];
    const float* Wb1  = (const float*)d_in[8];
    const float* bb1  = (const float*)d_in[9];
    const float* gb1  = (const float*)d_in[10];
    const float* beb1 = (const float*)d_in[11];
    const float* Wb2  = (const float*)d_in[12];
    const float* bb2  = (const float*)d_in[13];
    float* out = (float*)d_out;

    cudaFuncSetAttribute(k2_hmma, cudaFuncAttributeMaxDynamicSharedMemorySize,
                         SMEM_K2);
    cudaFuncSetAttribute(k3_hconv, cudaFuncAttributeMaxDynamicSharedMemorySize,
                         SMEM_K3);

    k1_hyper<<<ROWS, Hv>>>(z, W1, b1, g1, be1, Wb1, bb1, gb1, beb1, Wb2, bb2);

    dim3 gp(NWv/32, Hv/32);          // (384, 4)
    k_prep<<<gp, 256>>>(W2);

    dim3 g2(NWv/128, ROWS/128);      // (96, 64)
    k2_hmma<<<g2, 256, SMEM_K2>>>(b2);

    k3_hconv<<<Bv*(Lv/8), 256, SMEM_K3>>>(x, out);
}

// round 14
// speedup vs baseline: 1.6735x; 1.2873x over previous
#include <cuda_runtime.h>
#include <cuda_bf16.h>
#include <cstdint>

#define S2v 32
#define Bv  32
#define CIv 64
#define COv 64
#define Lv  256
#define Kv  3
#define Av  16
#define Hv  128
#define NWv (CIv*COv*Kv)   /* 12288 */
#define EPSv 1e-5f
#define ROWS (Bv*Lv)       /* 8192 */

// ---------------- device scratch (allocation-free) ----------------
__device__ __nv_bfloat16 g_Ah[ROWS*Hv];            // hi(h)
__device__ __nv_bfloat16 g_Al[ROWS*Hv];            // lo(h)
__device__ __nv_bfloat16 g_Bh[(size_t)NWv*Hv];     // hi(W2^T) permuted rows
__device__ __nv_bfloat16 g_Bl[(size_t)NWv*Hv];
__device__ float g_bias[ROWS*COv];
__device__ __nv_bfloat16 g_wh[(size_t)ROWS*NWv];   // 201 MB  hi(w), cols [k][o][i]
__device__ __nv_bfloat16 g_wl[(size_t)ROWS*NWv];   // 201 MB  lo(w)

// ---------------- helpers ----------------
__device__ __forceinline__ uint32_t s2u(const void* p) {
    uint32_t a;
    asm("{ .reg .u64 t; cvta.to.shared.u64 t, %1; cvt.u32.u64 %0, t; }"
        : "=r"(a) : "l"(p));
    return a;
}
__device__ __forceinline__ void mma16816(float* c, uint32_t a0, uint32_t a1,
                                         uint32_t a2, uint32_t a3,
                                         uint32_t b0, uint32_t b1)
{
    asm volatile(
        "mma.sync.aligned.m16n8k16.row.col.f32.bf16.bf16.f32 "
        "{%0,%1,%2,%3}, {%4,%5,%6,%7}, {%8,%9}, {%0,%1,%2,%3};"
        : "+f"(c[0]), "+f"(c[1]), "+f"(c[2]), "+f"(c[3])
        : "r"(a0), "r"(a1), "r"(a2), "r"(a3), "r"(b0), "r"(b1));
}
__device__ __forceinline__ void ldm_x4(uint32_t* r, uint32_t addr) {
    asm volatile("ldmatrix.sync.aligned.m8n8.x4.shared.b16 {%0,%1,%2,%3}, [%4];"
        : "=r"(r[0]), "=r"(r[1]), "=r"(r[2]), "=r"(r[3]) : "r"(addr));
}
__device__ __forceinline__ void ldm_x2(uint32_t* r, uint32_t addr) {
    asm volatile("ldmatrix.sync.aligned.m8n8.x2.shared.b16 {%0,%1}, [%2];"
        : "=r"(r[0]), "=r"(r[1]) : "r"(addr));
}
#define CP16(dst, src) \
    asm volatile("cp.async.cg.shared.global [%0], [%1], 16;" :: "r"(dst), "l"(src))
#define CPCOMMIT() asm volatile("cp.async.commit_group;")
#define CPWAIT(n)  asm volatile("cp.async.wait_group %0;" :: "n"(n))

// ---------------------------------------------------------------------------
// K1: hypernet rows. One block per (b,l) row, 128 threads.
// ---------------------------------------------------------------------------
__global__ void k1_hyper(const float* __restrict__ z,
                         const float* __restrict__ W1,  const float* __restrict__ b1,
                         const float* __restrict__ g1,  const float* __restrict__ be1,
                         const float* __restrict__ Wb1, const float* __restrict__ bb1,
                         const float* __restrict__ gb1, const float* __restrict__ beb1,
                         const float* __restrict__ Wb2, const float* __restrict__ bb2)
{
    int r = blockIdx.x;
    int j = threadIdx.x;
    __shared__ float sz[Av];
    __shared__ float s_hb[Hv];
    __shared__ float red[8];

    if (j < Av) sz[j] = z[r*Av + j];
    __syncthreads();

    float acc = b1[j];
#pragma unroll
    for (int a = 0; a < Av; a++) acc += sz[a] * W1[a*Hv + j];

    float v = acc, v2 = acc*acc;
#pragma unroll
    for (int off = 16; off > 0; off >>= 1) {
        v  += __shfl_xor_sync(0xffffffffu, v,  off);
        v2 += __shfl_xor_sync(0xffffffffu, v2, off);
    }
    int wid = j >> 5, lid = j & 31;
    if (lid == 0) { red[wid] = v; red[4 + wid] = v2; }
    __syncthreads();
    float sum = red[0] + red[1] + red[2] + red[3];
    float sq  = red[4] + red[5] + red[6] + red[7];
    float mu  = sum * (1.0f/Hv);
    float var = sq  * (1.0f/Hv) - mu*mu;
    float hn  = (acc - mu) * rsqrtf(var + EPSv) * g1[j] + be1[j];
    hn = fmaxf(hn, 0.0f);
    __nv_bfloat16 hi = __float2bfloat16(hn);
    g_Ah[r*Hv + j] = hi;
    g_Al[r*Hv + j] = __float2bfloat16(hn - __bfloat162float(hi));
    __syncthreads();

    float accb = bb1[j];
#pragma unroll
    for (int a = 0; a < Av; a++) accb += sz[a] * Wb1[a*Hv + j];

    float u = accb, u2 = accb*accb;
#pragma unroll
    for (int off = 16; off > 0; off >>= 1) {
        u  += __shfl_xor_sync(0xffffffffu, u,  off);
        u2 += __shfl_xor_sync(0xffffffffu, u2, off);
    }
    if (lid == 0) { red[wid] = u; red[4 + wid] = u2; }
    __syncthreads();
    float sumb = red[0] + red[1] + red[2] + red[3];
    float sqb  = red[4] + red[5] + red[6] + red[7];
    float mub  = sumb * (1.0f/Hv);
    float varb = sqb  * (1.0f/Hv) - mub*mub;
    float hbn  = (accb - mub) * rsqrtf(varb + EPSv) * gb1[j] + beb1[j];
    hbn = fmaxf(hbn, 0.0f);
    s_hb[j] = hbn;
    __syncthreads();

    if (j < COv) {
        float bo = bb2[j];
#pragma unroll 8
        for (int hh = 0; hh < Hv; hh++) bo += s_hb[hh] * Wb2[hh*COv + j];
        g_bias[r*COv + j] = bo;
    }
}

// ---------------------------------------------------------------------------
// K-prep: transpose + split + PERMUTE W2[128, 12288] -> Bh/Bl rows n' = k*4096+o*64+i
// ---------------------------------------------------------------------------
__global__ void k_prep(const float* __restrict__ W2)
{
    __shared__ float t[32][33];
    int n0 = blockIdx.x * 32;
    int k0 = blockIdx.y * 32;
    int tx = threadIdx.x & 31, ty = threadIdx.x >> 5;   // 32 x 8

#pragma unroll
    for (int i = 0; i < 4; i++) {
        int k = k0 + ty + i*8;
        t[ty + i*8][tx] = W2[(size_t)k * NWv + n0 + tx];
    }
    __syncthreads();
#pragma unroll
    for (int i = 0; i < 4; i++) {
        int n = n0 + ty + i*8;
        int i_ = n / 192, rest = n % 192;
        int o_ = rest / 3, k_ = rest % 3;
        int np = k_*4096 + o_*64 + i_;
        float val = t[tx][ty + i*8];
        __nv_bfloat16 hi = __float2bfloat16(val);
        g_Bh[(size_t)np * Hv + k0 + tx] = hi;
        g_Bl[(size_t)np * Hv + k0 + tx] = __float2bfloat16(val - __bfloat162float(hi));
    }
}

// ---------------------------------------------------------------------------
// K2-HMMA: g_wh/g_wl[8192, 12288(perm)] = bf16split(h @ W2p + b2p)
// 128x128 tile, K=128, cp.async 2-phase pipeline, split-3 MMA.
// Epilogue staged through smem for coalesced 16B stores (16B-aligned stride).
// ---------------------------------------------------------------------------
#define PADB 272
#define OFF_AH 0
#define OFF_AL 34816
#define OFF_BH 69632
#define OFF_BL 104448
#define SMEM_K2 139264
#define EPI_STRIDE 272        /* 17*16: 16B-aligned rows */

__device__ __forceinline__ void k2_split_mma(const char* Ab, const char* Bb,
                                             float acc[4][4][4])
{
#pragma unroll
    for (int ks = 0; ks < 8; ks++) {
        uint32_t br0[4], br1[4];
#pragma unroll
        for (int nf = 0; nf < 4; nf++) {
            br0[nf] = *(const uint32_t*)(Bb + nf*2176 + ks*32);
            br1[nf] = *(const uint32_t*)(Bb + nf*2176 + ks*32 + 16);
        }
#pragma unroll
        for (int mf = 0; mf < 4; mf++) {
            const char* Am = Ab + mf*4352 + ks*32;
            uint32_t a0 = *(const uint32_t*)(Am);
            uint32_t a1 = *(const uint32_t*)(Am + 2176);
            uint32_t a2 = *(const uint32_t*)(Am + 16);
            uint32_t a3 = *(const uint32_t*)(Am + 2192);
#pragma unroll
            for (int nf = 0; nf < 4; nf++)
                mma16816(acc[mf][nf], a0, a1, a2, a3, br0[nf], br1[nf]);
        }
    }
}

__global__ void __launch_bounds__(256, 1)
k2_hmma(const float* __restrict__ b2)
{
    extern __shared__ char sm[];
    uint32_t smu = s2u(sm);
    const int tid  = threadIdx.x;
    const int wid  = tid >> 5, lane = tid & 31;
    const int row0 = blockIdx.y * 128;
    const int col0 = blockIdx.x * 128;
    const int wm   = (wid >> 2) * 64;
    const int wn   = (wid & 3) * 32;

    // phase-0 loads: Ah, Bh
    for (int u = tid; u < 2048; u += 256) {
        int r = u >> 4, j = u & 15;
        CP16(smu + OFF_AH + r*PADB + j*16, &g_Ah[(size_t)(row0 + r)*Hv + j*8]);
    }
    for (int u = tid; u < 2048; u += 256) {
        int r = u >> 4, j = u & 15;
        CP16(smu + OFF_BH + r*PADB + j*16, &g_Bh[(size_t)(col0 + r)*Hv + j*8]);
    }
    CPCOMMIT();
    // phase-1 loads: Al, Bl
    for (int u = tid; u < 2048; u += 256) {
        int r = u >> 4, j = u & 15;
        CP16(smu + OFF_AL + r*PADB + j*16, &g_Al[(size_t)(row0 + r)*Hv + j*8]);
    }
    for (int u = tid; u < 2048; u += 256) {
        int r = u >> 4, j = u & 15;
        CP16(smu + OFF_BL + r*PADB + j*16, &g_Bl[(size_t)(col0 + r)*Hv + j*8]);
    }
    CPCOMMIT();

    float acc[4][4][4];
#pragma unroll
    for (int mf = 0; mf < 4; mf++)
#pragma unroll
        for (int nf = 0; nf < 4; nf++)
#pragma unroll
            for (int q = 0; q < 4; q++) acc[mf][nf][q] = 0.0f;

    const int aoff = (wm + (lane >> 2)) * PADB + (lane & 3) * 4;
    const int boff = (wn + (lane >> 2)) * PADB + (lane & 3) * 4;

    CPWAIT(1);
    __syncthreads();
    k2_split_mma(sm + OFF_AH + aoff, sm + OFF_BH + boff, acc);   // Ah*Bh
    CPWAIT(0);
    __syncthreads();
    k2_split_mma(sm + OFF_AH + aoff, sm + OFF_BL + boff, acc);   // Ah*Bl
    k2_split_mma(sm + OFF_AL + aoff, sm + OFF_BH + boff, acc);   // Al*Bh

    // bias (permuted) per output column
    float bv[4][2];
#pragma unroll
    for (int nf = 0; nf < 4; nf++) {
#pragma unroll
        for (int e = 0; e < 2; e++) {
            int c = col0 + wn + nf*8 + (lane & 3)*2 + e;
            int i_ = c & 63, o_ = (c >> 6) & 63, kt = c >> 12;
            bv[nf][e] = b2[i_*192 + o_*3 + kt];
        }
    }

    __syncthreads();   // all smem A/B reads done; reuse as staging
    char* stH = sm;                       // 128 x 272 = 34816 B
    char* stL = sm + 34816;               // 128 x 272

#pragma unroll
    for (int mf = 0; mf < 4; mf++) {
#pragma unroll
        for (int nf = 0; nf < 4; nf++) {
            int cl = wn + nf*8 + (lane & 3)*2;
#pragma unroll
            for (int half = 0; half < 2; half++) {
                int rl = wm + mf*16 + (lane >> 2) + half*8;
                float v0 = acc[mf][nf][half*2+0] + bv[nf][0];
                float v1 = acc[mf][nf][half*2+1] + bv[nf][1];
                __nv_bfloat16 h0 = __float2bfloat16(v0);
                __nv_bfloat16 h1 = __float2bfloat16(v1);
                __nv_bfloat162 hh; hh.x = h0; hh.y = h1;
                __nv_bfloat162 ll;
                ll.x = __float2bfloat16(v0 - __bfloat162float(h0));
                ll.y = __float2bfloat16(v1 - __bfloat162float(h1));
                *(__nv_bfloat162*)(stH + rl*EPI_STRIDE + cl*2) = hh;
                *(__nv_bfloat162*)(stL + rl*EPI_STRIDE + cl*2) = ll;
            }
        }
    }
    __syncthreads();

    // coalesced drain: 16B chunks, contiguous per row
    for (int u = tid; u < 2048; u += 256) {
        int r = u >> 4, ch = u & 15;
        uint4 vh = *(const uint4*)(stH + r*EPI_STRIDE + ch*16);
        uint4 vl = *(const uint4*)(stL + r*EPI_STRIDE + ch*16);
        size_t idx = (size_t)(row0 + r) * NWv + col0 + ch*8;
        *(uint4*)&g_wh[idx] = vh;
        *(uint4*)&g_wl[idx] = vl;
    }
}

// ---------------------------------------------------------------------------
// K3-HMMA: conv via tensor cores. CTA = (b, 4 l's). 256 threads, ~109KB smem
// -> 2 CTAs/SM so sibling CTA hides synchronous w-load latency.
// Proven R6 structure: plain LDG->STS w staging, ldmatrix + mma, register acc.
// ---------------------------------------------------------------------------
#define X_STRIDE 144
#define XH_O 0                       /* [6][32][144B] = 27648 */
#define XL_O 27648
#define WH_O 55296                   /* [192][144B] = 27648 */
#define WL_O 82944
#define BIA_O 110592                 /* 4*64 floats = 1024 */
#define SMEM_K3 111616

__global__ void __launch_bounds__(256, 2)
k3_hconv(const float* __restrict__ x, float* __restrict__ out)
{
    extern __shared__ char sm[];
    uint32_t smu = s2u(sm);
    const int tid  = threadIdx.x;
    const int wid  = tid >> 5, lane = tid & 31;
    const int b  = blockIdx.x >> 6;
    const int l0 = (blockIdx.x & 63) * 4;
    const int r0 = b*Lv + l0;

    // ---- stage x window [l0-1, l0+4] as bf16 hi/lo, layout [l''][s][i] ----
    for (int u = tid; u < 2048; u += 256) {
        int s = u >> 6, i = u & 63;
        const float* xp = x + ((size_t)(s*Bv + b)*CIv + i)*Lv;
#pragma unroll
        for (int t = 0; t < 6; t++) {
            int l = l0 - 1 + t;
            float v = (l >= 0 && l < Lv) ? __ldg(xp + l) : 0.0f;
            __nv_bfloat16 hi = __float2bfloat16(v);
            *(__nv_bfloat16*)(sm + XH_O + (t*32 + s)*X_STRIDE + i*2) = hi;
            *(__nv_bfloat16*)(sm + XL_O + (t*32 + s)*X_STRIDE + i*2) =
                __float2bfloat16(v - __bfloat162float(hi));
        }
    }
    // ---- stage bias [dl][o] ----
    for (int u = tid; u < 256; u += 256)
        ((float*)(sm + BIA_O))[u] = g_bias[(r0 + (u >> 6))*COv + (u & 63)];
    if (tid < 256) {  // remaining bias entries (256 total: 4*64)
        // covered above since 256 threads handle u=tid exactly once (u<256)
    }

    const int mt = wid & 1, q = wid >> 1;
    const uint32_t a_lane = (uint32_t)((lane & 15)*X_STRIDE + (lane >> 4)*16);
    const uint32_t b_lane = (uint32_t)((lane & 7)*X_STRIDE + ((lane >> 3) & 1)*16);

    float acc[4][2][4];
#pragma unroll
    for (int dl = 0; dl < 4; dl++)
#pragma unroll
        for (int nt = 0; nt < 2; nt++)
#pragma unroll
            for (int e = 0; e < 4; e++) acc[dl][nt][e] = 0.0f;

    for (int dl = 0; dl < 4; dl++) {
        __syncthreads();   // xs/bias ready (dl=0) / prior w reads done
        // ---- stage w row (hi/lo), [192 rows][128B] with 16B row pad ----
        {
            const __nv_bfloat16* srcH = g_wh + (size_t)(r0 + dl) * NWv;
            const __nv_bfloat16* srcL = g_wl + (size_t)(r0 + dl) * NWv;
            for (int u = tid; u < 1536; u += 256) {
                int r = u >> 3, c8 = u & 7;
                *(uint4*)(sm + WH_O + r*X_STRIDE + c8*16) =
                    *(const uint4*)(srcH + r*64 + c8*8);
                *(uint4*)(sm + WL_O + r*X_STRIDE + c8*16) =
                    *(const uint4*)(srcL + r*64 + c8*8);
            }
        }
        __syncthreads();

#pragma unroll
        for (int kt = 0; kt < 3; kt++) {
            uint32_t xrow = (uint32_t)(((dl + kt)*32 + mt*16) * X_STRIDE);
            uint32_t wrow = (uint32_t)((kt*64 + q*16) * X_STRIDE);
#pragma unroll
            for (int ks = 0; ks < 4; ks++) {
                uint32_t col = ks*32;
                uint32_t ah[4], al[4], bh0[2], bh1[2], bl0[2], bl1[2];
                ldm_x4(ah, smu + XH_O + xrow + a_lane + col);
                ldm_x4(al, smu + XL_O + xrow + a_lane + col);
                ldm_x2(bh0, smu + WH_O + wrow + b_lane + col);
                ldm_x2(bh1, smu + WH_O + wrow + 8*X_STRIDE + b_lane + col);
                ldm_x2(bl0, smu + WL_O + wrow + b_lane + col);
                ldm_x2(bl1, smu + WL_O + wrow + 8*X_STRIDE + b_lane + col);
                mma16816(acc[dl][0], ah[0],ah[1],ah[2],ah[3], bh0[0],bh0[1]);
                mma16816(acc[dl][0], ah[0],ah[1],ah[2],ah[3], bl0[0],bl0[1]);
                mma16816(acc[dl][0], al[0],al[1],al[2],al[3], bh0[0],bh0[1]);
                mma16816(acc[dl][1], ah[0],ah[1],ah[2],ah[3], bh1[0],bh1[1]);
                mma16816(acc[dl][1], ah[0],ah[1],ah[2],ah[3], bl1[0],bl1[1]);
                mma16816(acc[dl][1], al[0],al[1],al[2],al[3], bh1[0],bh1[1]);
            }
        }
    }

    // ---- direct output: each thread owns 8 (s,o) pairs x 4 l's (16B each) ----
    {
        const float* bs = (const float*)(sm + BIA_O);
        int m = lane >> 2, n2 = (lane & 3)*2;
#pragma unroll
        for (int nt = 0; nt < 2; nt++) {
#pragma unroll
            for (int sh = 0; sh < 2; sh++) {
#pragma unroll
                for (int oc = 0; oc < 2; oc++) {
                    int s = mt*16 + m + sh*8;
                    int o = q*16 + nt*8 + n2 + oc;
                    int e = sh*2 + oc;
                    float4 v;
                    v.x = acc[0][nt][e] + bs[0*64 + o];
                    v.y = acc[1][nt][e] + bs[1*64 + o];
                    v.z = acc[2][nt][e] + bs[2*64 + o];
                    v.w = acc[3][nt][e] + bs[3*64 + o];
                    *(float4*)(out + ((size_t)(s*Bv + b)*COv + o)*Lv + l0) = v;
                }
            }
        }
    }
}

// ---------------------------------------------------------------------------
extern "C" void kernel_launch(void* const* d_in, const int* in_sizes, int n_in,
                              void* d_out, int out_size)
{
    const float* x    = (const float*)d_in[0];
    const float* z    = (const float*)d_in[1];
    const float* W1   = (const float*)d_in[2];
    const float* b1   = (const float*)d_in[3];
    const float* g1   = (const float*)d_in[4];
    const float* be1  = (const float*)d_in[5];
    const float* W2   = (const float*)d_in[6];
    const float* b2   = (const float*)d_in[7];
    const float* Wb1  = (const float*)d_in[8];
    const float* bb1  = (const float*)d_in[9];
    const float* gb1  = (const float*)d_in[10];
    const float* beb1 = (const float*)d_in[11];
    const float* Wb2  = (const float*)d_in[12];
    const float* bb2  = (const float*)d_in[13];
    float* out = (float*)d_out;

    cudaFuncSetAttribute(k2_hmma, cudaFuncAttributeMaxDynamicSharedMemorySize,
                         SMEM_K2);
    cudaFuncSetAttribute(k3_hconv, cudaFuncAttributeMaxDynamicSharedMemorySize,
                         SMEM_K3);

    k1_hyper<<<ROWS, Hv>>>(z, W1, b1, g1, be1, Wb1, bb1, gb1, beb1, Wb2, bb2);

    dim3 gp(NWv/32, Hv/32);          // (384, 4)
    k_prep<<<gp, 256>>>(W2);

    dim3 g2(NWv/128, ROWS/128);      // (96, 64)
    k2_hmma<<<g2, 256, SMEM_K2>>>(b2);

    k3_hconv<<<Bv*(Lv/4), 256, SMEM_K3>>>(x, out);
}